// round 16
// baseline (speedup 1.0000x reference)
#include <cuda_runtime.h>
#include <cuda_bf16.h>
#include <cuda_fp16.h>
#include <math.h>
#include <stdint.h>

#define BATCH 4
#define CDIM 128
#define INNER 512
#define NQ 4096
#define NK 512
#define NHEADS 8
#define DHEAD 64

// ---------------- scratch (static device globals; allocation-free) ----------
__device__ float g_qdw[BATCH * CDIM * NQ];     // 8 MB   depthwise-q + BN
__device__ float g_kvdw[BATCH * CDIM * NK];    // 1 MB   depthwise-kv + BN
__device__ float g_q[BATCH * INNER * NQ];      // 32 MB  q after pointwise
__device__ float g_kv[BATCH * 2 * INNER * NK]; // 8 MB   kv after pointwise
__device__ float g_att[BATCH * INNER * NQ];    // 32 MB  attention output

// ---------------------------------------------------------------------------
// Kernel 1: both depthwise 3x3x3 convs (stride1 and stride2) + batchnorm.
// ---------------------------------------------------------------------------
__global__ __launch_bounds__(256) void dw_bn_kernel(
    const float* __restrict__ x,
    const float* __restrict__ wq,
    const float* __restrict__ qg, const float* __restrict__ qb,
    const float* __restrict__ qm, const float* __restrict__ qv,
    const float* __restrict__ wkv,
    const float* __restrict__ kg, const float* __restrict__ kb,
    const float* __restrict__ km, const float* __restrict__ kvvar)
{
    __shared__ float s[18 * 18 * 18];
    __shared__ float swq[27], swkv[27];
    const int c = blockIdx.x, b = blockIdx.y;
    const int tid = threadIdx.x;

    const float* xp = x + ((size_t)(b * CDIM + c)) * NQ;
    for (int idx = tid; idx < 5832; idx += 256) {
        int z = idx / 324; int r = idx - z * 324;
        int y = r / 18;    int xx = r - y * 18;
        z -= 1; y -= 1; xx -= 1;
        float v = 0.f;
        if ((unsigned)z < 16u && (unsigned)y < 16u && (unsigned)xx < 16u)
            v = xp[(z * 16 + y) * 16 + xx];
        s[idx] = v;
    }
    if (tid < 27) { swq[tid] = wq[c * 27 + tid]; swkv[tid] = wkv[c * 27 + tid]; }

    const float qscale = qg[c] * rsqrtf(qv[c] + 1e-5f);
    const float qshift = qb[c] - qm[c] * qscale;
    const float kscale = kg[c] * rsqrtf(kvvar[c] + 1e-5f);
    const float kshift = kb[c] - km[c] * kscale;
    __syncthreads();

    float* qo = g_qdw + ((size_t)(b * CDIM + c)) * NQ;
    for (int o = tid; o < 4096; o += 256) {
        const int z = o >> 8, y = (o >> 4) & 15, xx = o & 15;
        float sum = 0.f;
        #pragma unroll
        for (int dz = 0; dz < 3; dz++)
            #pragma unroll
            for (int dy = 0; dy < 3; dy++)
                #pragma unroll
                for (int dx = 0; dx < 3; dx++)
                    sum += swq[dz * 9 + dy * 3 + dx] *
                           s[(z + dz) * 324 + (y + dy) * 18 + (xx + dx)];
        qo[o] = sum * qscale + qshift;
    }

    float* ko = g_kvdw + ((size_t)(b * CDIM + c)) * NK;
    for (int o = tid; o < 512; o += 256) {
        const int z = o >> 6, y = (o >> 3) & 7, xx = o & 7;
        float sum = 0.f;
        #pragma unroll
        for (int dz = 0; dz < 3; dz++)
            #pragma unroll
            for (int dy = 0; dy < 3; dy++)
                #pragma unroll
                for (int dx = 0; dx < 3; dx++)
                    sum += swkv[dz * 9 + dy * 3 + dx] *
                           s[(2 * z + dz) * 324 + (2 * y + dy) * 18 + (2 * xx + dx)];
        ko[o] = sum * kscale + kshift;
    }
}

// ===========================================================================
// tcgen05 helpers
// ===========================================================================
__device__ __forceinline__ uint32_t s2u(const void* p) {
    uint32_t a;
    asm("{ .reg .u64 t; cvta.to.shared.u64 t, %1; cvt.u32.u64 %0, t; }"
        : "=r"(a) : "l"(p));
    return a;
}
__device__ __forceinline__ uint32_t elect1() {
    uint32_t pred;
    asm volatile("{\n\t.reg .pred p;\n\telect.sync _|p, 0xFFFFFFFF;\n\t"
                 "selp.b32 %0, 1, 0, p;\n\t}" : "=r"(pred));
    return pred;
}
__device__ __forceinline__ void mbar_init(uint32_t mbar, uint32_t cnt) {
    asm volatile("mbarrier.init.shared.b64 [%0], %1;" :: "r"(mbar), "r"(cnt) : "memory");
}
__device__ __forceinline__ void mbar_inval(uint32_t mbar) {
    asm volatile("mbarrier.inval.shared.b64 [%0];" :: "r"(mbar) : "memory");
}
__device__ __forceinline__ void mbar_wait(uint32_t mbar, uint32_t parity) {
    asm volatile(
        "{\n\t.reg .pred P1;\n\t"
        "WL%=:\n\t"
        "mbarrier.try_wait.parity.acquire.cta.shared::cta.b64 P1, [%0], %1, 0x989680;\n\t"
        "@P1 bra.uni WD%=;\n\t"
        "bra.uni WL%=;\n\t"
        "WD%=:\n\t}"
        :: "r"(mbar), "r"(parity) : "memory");
}
__device__ __forceinline__ void tmem_alloc(uint32_t smem_dst, uint32_t ncols) {
    asm volatile("tcgen05.alloc.cta_group::1.sync.aligned.shared::cta.b32 [%0], %1;"
                 :: "r"(smem_dst), "r"(ncols) : "memory");
}
__device__ __forceinline__ void tmem_dealloc(uint32_t tmem, uint32_t ncols) {
    asm volatile("tcgen05.relinquish_alloc_permit.cta_group::1.sync.aligned;");
    asm volatile("tcgen05.dealloc.cta_group::1.sync.aligned.b32 %0, %1;"
                 :: "r"(tmem), "r"(ncols));
}
__device__ __forceinline__ void mma_f16_ss(uint32_t d, uint64_t a, uint64_t b,
                                           uint32_t idesc, uint32_t en) {
    asm volatile(
        "{\n\t.reg .pred p;\n\tsetp.ne.u32 p, %5, 0;\n\t"
        "tcgen05.mma.cta_group::1.kind::f16 [%0], %1, %2, %3, {%4, %4, %4, %4}, p;\n\t}"
        :: "r"(d), "l"(a), "l"(b), "r"(idesc), "r"(0u), "r"(en) : "memory");
}
__device__ __forceinline__ void mma_f16_ts(uint32_t d, uint32_t a_tmem, uint64_t b,
                                           uint32_t idesc, uint32_t en) {
    asm volatile(
        "{\n\t.reg .pred p;\n\tsetp.ne.u32 p, %5, 0;\n\t"
        "tcgen05.mma.cta_group::1.kind::f16 [%0], [%1], %2, %3, {%4, %4, %4, %4}, p;\n\t}"
        :: "r"(d), "r"(a_tmem), "l"(b), "r"(idesc), "r"(0u), "r"(en) : "memory");
}
__device__ __forceinline__ void tc_commit(uint32_t mbar) {
    asm volatile(
        "tcgen05.commit.cta_group::1.mbarrier::arrive::one.shared::cluster.b64 [%0];"
        :: "r"(mbar) : "memory");
}
__device__ __forceinline__ float ex2f(float x) {
    float r;
    asm("ex2.approx.f32 %0, %1;" : "=f"(r) : "f"(x));
    return r;
}
#define TC_FENCE_AFTER()  asm volatile("tcgen05.fence::after_thread_sync;" ::: "memory")
#define TC_FENCE_BEFORE() asm volatile("tcgen05.fence::before_thread_sync;" ::: "memory")
#define TC_WAIT_LD()      asm volatile("tcgen05.wait::ld.sync.aligned;" ::: "memory")
#define TC_WAIT_ST()      asm volatile("tcgen05.wait::st.sync.aligned;" ::: "memory")
#define FENCE_ASYNC()     asm volatile("fence.proxy.async.shared::cta;" ::: "memory")

#define TC_LD_X32(r, addr) \
    asm volatile( \
        "tcgen05.ld.sync.aligned.32x32b.x32.b32 " \
        "{%0, %1, %2, %3, %4, %5, %6, %7, " \
        " %8, %9, %10, %11, %12, %13, %14, %15, " \
        " %16, %17, %18, %19, %20, %21, %22, %23, " \
        " %24, %25, %26, %27, %28, %29, %30, %31}, [%32];" \
        : "=r"((r)[0]),  "=r"((r)[1]),  "=r"((r)[2]),  "=r"((r)[3]), \
          "=r"((r)[4]),  "=r"((r)[5]),  "=r"((r)[6]),  "=r"((r)[7]), \
          "=r"((r)[8]),  "=r"((r)[9]),  "=r"((r)[10]), "=r"((r)[11]), \
          "=r"((r)[12]), "=r"((r)[13]), "=r"((r)[14]), "=r"((r)[15]), \
          "=r"((r)[16]), "=r"((r)[17]), "=r"((r)[18]), "=r"((r)[19]), \
          "=r"((r)[20]), "=r"((r)[21]), "=r"((r)[22]), "=r"((r)[23]), \
          "=r"((r)[24]), "=r"((r)[25]), "=r"((r)[26]), "=r"((r)[27]), \
          "=r"((r)[28]), "=r"((r)[29]), "=r"((r)[30]), "=r"((r)[31]) \
        : "r"(addr))

#define TC_ST_X16(addr, r) \
    asm volatile( \
        "tcgen05.st.sync.aligned.32x32b.x16.b32 [%0], " \
        "{%1, %2, %3, %4, %5, %6, %7, %8, " \
        " %9, %10, %11, %12, %13, %14, %15, %16};" \
        :: "r"(addr), \
           "r"((r)[0]),  "r"((r)[1]),  "r"((r)[2]),  "r"((r)[3]), \
           "r"((r)[4]),  "r"((r)[5]),  "r"((r)[6]),  "r"((r)[7]), \
           "r"((r)[8]),  "r"((r)[9]),  "r"((r)[10]), "r"((r)[11]), \
           "r"((r)[12]), "r"((r)[13]), "r"((r)[14]), "r"((r)[15]) \
        : "memory")

// SW128 smem descriptor base (layout=2, version=1, SBO=64, LBO=1)
#define DESC_BASE ((2ULL << 61) | (1ULL << 46) | (64ULL << 32) | (1ULL << 16))
#define MK_DESC(a) (DESC_BASE | ((uint64_t)((a) >> 4) & 0x3FFFULL))

__device__ __forceinline__ uint32_t sw128(uint32_t o) { return o ^ ((o >> 3) & 0x70); }
// rows x 64 elems (128B rows), SW128
__device__ __forceinline__ uint32_t qk_off(int r, int c) {
    return sw128((uint32_t)r * 128u + (uint32_t)c * 2u);
}
// 128 x (64*ac) 2B elems, blocked-atom, 16 atom-rows per atom-col
__device__ __forceinline__ uint32_t p_off(int i, int j) {
    uint32_t o = ((uint32_t)(i >> 3) + (uint32_t)(j >> 6) * 16u) * 1024u +
                 (uint32_t)(i & 7) * 128u + (uint32_t)(j & 63) * 2u;
    return sw128(o);
}
// 64 x 256 fp16 blocked-atom (8 atom-rows per atom-col)
__device__ __forceinline__ uint32_t v_off(int d, int j) {
    uint32_t o = ((uint32_t)(d >> 3) + (uint32_t)(j >> 6) * 8u) * 1024u +
                 (uint32_t)(d & 7) * 128u + (uint32_t)(j & 63) * 2u;
    return sw128(o);
}

// idesc: dtype F32 (1<<4); atype/btype F16=0; M=128 (8<<24); N bits 17..22
#define IDESC_F16_N(n)  ((1u << 4) | (((n) / 8) << 17) | (8u << 24))

// ===========================================================================
// Kernel 2: tcgen05 GEMM, plain fp16 operands (single term). 66 KB smem ->
// 3 CTAs/SM. grid (N/128, M/128, BATCH), 512 threads.
// ===========================================================================
#define GM_MISC 0
#define GM_A    1024
#define GM_B    (GM_A + 32768)
#define GM_REQ  (GM_B + 32768 + 1024)

__global__ __launch_bounds__(512, 1)
void gemm_tc_kernel(const float* __restrict__ A, const float* __restrict__ Bm,
                    float* __restrict__ Cm, int M, int N, int K,
                    const float* __restrict__ bias)
{
#if defined(__CUDA_ARCH_FEAT_SM103_ALL)
    extern __shared__ char sm_raw[];
    char* base = (char*)(((uintptr_t)sm_raw + 1023) & ~(uintptr_t)1023);
    const uint32_t sb = s2u(base);

    const int tid = threadIdx.x, w = tid >> 5, lane = tid & 31;
    const int sub = w & 3, grp = w >> 2;
    const int row = sub * 32 + lane;
    const int n0 = blockIdx.x * 128, m0 = blockIdx.y * 128, bz = blockIdx.z;

    const uint32_t misc = sb + GM_MISC;
    const uint32_t mbar = misc + 8;
    if (w == 0) tmem_alloc(misc, 128);
    if (tid == 0) mbar_init(mbar, 1);
    __syncthreads();
    uint32_t tmem;
    asm volatile("ld.shared.b32 %0, [%1];" : "=r"(tmem) : "r"(misc));

    const float* Bp = Bm + (size_t)bz * K * N;
    float* Cp = Cm + (size_t)bz * M * N;
    const int nchunks = K >> 7;

    for (int kc = 0; kc < nchunks; kc++) {
        const int k0 = kc << 7;
        for (int g = tid; g < 2048; g += 512) {
            const int m = g >> 4, kg = (g & 15) * 8;
            const float* as = A + (size_t)(m0 + m) * K + k0 + kg;
            float4 a0 = *(const float4*)(as);
            float4 a1 = *(const float4*)(as + 4);
            uint4 pk;
            ((__half2*)&pk)[0] = __floats2half2_rn(a0.x, a0.y);
            ((__half2*)&pk)[1] = __floats2half2_rn(a0.z, a0.w);
            ((__half2*)&pk)[2] = __floats2half2_rn(a1.x, a1.y);
            ((__half2*)&pk)[3] = __floats2half2_rn(a1.z, a1.w);
            *(uint4*)(base + GM_A + p_off(m, kg)) = pk;
        }
        for (int g = tid; g < 2048; g += 512) {
            const int n = g & 127, kg = (g >> 7) * 8;
            const float* bs = Bp + (size_t)(k0 + kg) * N + n0 + n;
            float f[8];
            #pragma unroll
            for (int j = 0; j < 8; j++) f[j] = bs[(size_t)j * N];
            uint4 pk;
            #pragma unroll
            for (int t = 0; t < 4; t++) {
                __half2 h2 = __floats2half2_rn(f[2 * t], f[2 * t + 1]);
                ((uint32_t*)&pk)[t] = *(uint32_t*)&h2;
            }
            *(uint4*)(base + GM_B + p_off(n, kg)) = pk;
        }
        FENCE_ASYNC();
        __syncthreads();

        if (w == 0) {
            TC_FENCE_AFTER();
            const uint64_t ad = MK_DESC(sb + GM_A);
            const uint64_t bd = MK_DESC(sb + GM_B);
            const uint32_t id = IDESC_F16_N(128);
            if (elect1()) {
                #pragma unroll
                for (int s = 0; s < 8; s++) {
                    uint64_t doff = (uint64_t)(s >> 2) * 1024 + (s & 3) * 2;
                    mma_f16_ss(tmem, ad + doff, bd + doff, id, !(kc == 0 && s == 0));
                }
                tc_commit(mbar);
            }
        }
        mbar_wait(mbar, kc & 1);
    }
    TC_FENCE_AFTER();

    {
        uint32_t r[32];
        TC_LD_X32(r, tmem + grp * 32);
        TC_WAIT_LD();
        TC_FENCE_BEFORE();
        const float bb = bias ? bias[m0 + row] : 0.f;
        float* cp = Cp + (size_t)(m0 + row) * N + n0 + grp * 32;
        float4 v;
        #pragma unroll
        for (int t = 0; t < 32; t += 4) {
            v = make_float4(__uint_as_float(r[t]) + bb,
                            __uint_as_float(r[t + 1]) + bb,
                            __uint_as_float(r[t + 2]) + bb,
                            __uint_as_float(r[t + 3]) + bb);
            *(float4*)(cp + t) = v;
        }
    }

    __syncthreads();
    if (tid == 0) mbar_inval(mbar);
    __syncthreads();
    if (w == 0) tmem_dealloc(tmem, 128);
#endif
}

// smem regions for attention (relative to 1024-aligned base)
#define SM_MISC 0
#define SM_Q    4096                 // 16 KB: Q fp16 [128 i][64 d]
#define SM_K    (SM_Q + 16384)       // 32 KB: K-half fp16 [256 j][64 d] -> sO
#define SM_V    (SM_K + 32768)       // 32 KB: V-half fp16 [64 d][256 j]
#define SM_REQ  (SM_V + 32768 + 1024)   // ~86 KB -> 2 CTAs/SM

// ===========================================================================
// Kernel 3: tcgen05 fused attention, 2 CTAs/SM co-resident.
// j processed in two 256-halves; TMEM = 256 cols/CTA:
//   dots fp32 cols 0-255 per half; warp-half gh (w>>2) owns cols
//   [128gh,128gh+128); P fp16x2 in place at [128gh,128gh+64) chunk-by-chunk;
//   D (N=64 fp32) at cols 64-127 (dead-dots window, disjoint from both P
//   regions); D drained to registers after each half and accumulated fp32.
// 256 threads, __launch_bounds__(256,2). grid (32, 8, 4).
// ===========================================================================
__global__ __launch_bounds__(256, 2)
void attn_tc_kernel(const float* __restrict__ gq,
                    const float* __restrict__ gkv,
                    float* __restrict__ gout)
{
#if defined(__CUDA_ARCH_FEAT_SM103_ALL)
    extern __shared__ char sm_raw[];
    char* base = (char*)(((uintptr_t)sm_raw + 1023) & ~(uintptr_t)1023);
    const uint32_t sb = s2u(base);

    const int tid = threadIdx.x, w = tid >> 5, lane = tid & 31;
    const int sub = w & 3, gh = w >> 2;      // subpartition / 128-col half
    const int row = sub * 32 + lane;         // q row owned in TMEM
    const int i0 = blockIdx.x * 128;
    const int h  = blockIdx.y;
    const int b  = blockIdx.z;

    const uint32_t misc  = sb + SM_MISC;
    const uint32_t mbar0 = misc + 8;         // MMA1 commits (parity = half)
    const uint32_t mbar2 = misc + 16;        // MMA2 commits (parity = half)
    float* sRow = (float*)(base + SM_MISC + 1024);   // [2][128]
    float* linv = (float*)(base + SM_MISC + 2176);   // [128]

    if (w == 0) tmem_alloc(misc, 256);
    if (tid == 0) { mbar_init(mbar0, 1); mbar_init(mbar2, 1); }
    __syncthreads();
    uint32_t tmem;
    asm volatile("ld.shared.b32 %0, [%1];" : "=r"(tmem) : "r"(misc));

    const float* qbase = gq  + ((size_t)b * INNER + h * DHEAD) * NQ + i0;
    const float* kbase = gkv + ((size_t)b * 2 * INNER + h * DHEAD) * NK;
    const float* vbase = kbase + (size_t)INNER * NK;

    // softmax base-2 trick: scale = 1/sqrt(64) * log2(e)
    const float QSCALE = 0.125f * 1.44269504088896341f;

    // ---- load Q fp16 (transpose [d][i]->[i][d], scaled) ----
    for (int g = tid; g < 1024; g += 256) {
        const int i = g & 127, d0 = (g >> 7) * 8;
        float f[8];
        #pragma unroll
        for (int k = 0; k < 8; k++)
            f[k] = qbase[(size_t)(d0 + k) * NQ + i] * QSCALE;
        uint4 pk;
        #pragma unroll
        for (int t = 0; t < 4; t++) {
            __half2 h2 = __floats2half2_rn(f[2 * t], f[2 * t + 1]);
            ((uint32_t*)&pk)[t] = *(uint32_t*)&h2;
        }
        *(uint4*)(base + SM_Q + qk_off(i, d0)) = pk;
    }
    // ---- load K half0 (transpose, j 0-255) ----
    for (int g = tid; g < 2048; g += 256) {
        const int j = g & 255, d0 = (g >> 8) * 8;
        float f[8];
        #pragma unroll
        for (int k = 0; k < 8; k++)
            f[k] = kbase[(size_t)(d0 + k) * NK + j];
        uint4 pk;
        #pragma unroll
        for (int t = 0; t < 4; t++) {
            __half2 h2 = __floats2half2_rn(f[2 * t], f[2 * t + 1]);
            ((uint32_t*)&pk)[t] = *(uint32_t*)&h2;
        }
        *(uint4*)(base + SM_K + qk_off(j, d0)) = pk;
    }
    // ---- load V half0 (j 0-255, blocked-atom) ----
    for (int g = tid; g < 2048; g += 256) {
        const int d = g >> 5, j8 = (g & 31) * 8;
        const float* vs = vbase + (size_t)d * NK + j8;
        float4 v0 = *(const float4*)(vs);
        float4 v1 = *(const float4*)(vs + 4);
        uint4 pk;
        ((__half2*)&pk)[0] = __floats2half2_rn(v0.x, v0.y);
        ((__half2*)&pk)[1] = __floats2half2_rn(v0.z, v0.w);
        ((__half2*)&pk)[2] = __floats2half2_rn(v1.x, v1.y);
        ((__half2*)&pk)[3] = __floats2half2_rn(v1.z, v1.w);
        *(uint4*)(base + SM_V + v_off(d, j8)) = pk;
    }
    FENCE_ASYNC();
    __syncthreads();

    float rsum = 0.f;
    float acc[32];
    #pragma unroll
    for (int t = 0; t < 32; t++) acc[t] = 0.f;

    #pragma unroll 1
    for (int hh = 0; hh < 2; hh++) {
        // ---- MMA1: dots(cols 0-255) = Q @ K_half^T (N=256, 4 K-steps) ----
        if (w == 0) {
            TC_FENCE_AFTER();
            const uint64_t qd = MK_DESC(sb + SM_Q);
            const uint64_t kd = MK_DESC(sb + SM_K);
            const uint32_t id1 = IDESC_F16_N(256);
            if (elect1()) {
                #pragma unroll
                for (int s = 0; s < 4; s++)
                    mma_f16_ss(tmem, qd + s * 2, kd + s * 2, id1, s > 0);
                tc_commit(mbar0);
            }
        }
        mbar_wait(mbar0, hh);
        TC_FENCE_AFTER();

        // ---- prefetch K half1 while exp runs (K half0 consumed) ----
        if (hh == 0) {
            for (int g = tid; g < 2048; g += 256) {
                const int j = g & 255, d0 = (g >> 8) * 8;
                float f[8];
                #pragma unroll
                for (int k = 0; k < 8; k++)
                    f[k] = kbase[(size_t)(d0 + k) * NK + 256 + j];
                uint4 pk;
                #pragma unroll
                for (int t = 0; t < 4; t++) {
                    __half2 h2 = __floats2half2_rn(f[2 * t], f[2 * t + 1]);
                    ((uint32_t*)&pk)[t] = *(uint32_t*)&h2;
                }
                *(uint4*)(base + SM_K + qk_off(j, d0)) = pk;
            }
        }

        // ---- exp: 4 chunks per warp; P fp16x2 in place within own region ----
        for (int c8 = 0; c8 < 4; c8++) {
            uint32_t r[32], pk[16];
            TC_LD_X32(r, tmem + gh * 128 + c8 * 32);
            TC_WAIT_LD();
            #pragma unroll
            for (int t = 0; t < 16; t++) {
                float e0 = ex2f(__uint_as_float(r[2 * t]));
                float e1 = ex2f(__uint_as_float(r[2 * t + 1]));
                rsum += e0 + e1;
                __half2 h2 = __floats2half2_rn(e0, e1);
                pk[t] = *(uint32_t*)&h2;
            }
            TC_ST_X16(tmem + gh * 128 + c8 * 16, pk);
            TC_WAIT_ST();
        }
        TC_FENCE_BEFORE();
        FENCE_ASYNC();
        __syncthreads();

        // ---- MMA2 (TS): D(cols 64-127) += P @ V_half^T (16 K-steps) ----
        if (w == 0) {
            TC_FENCE_AFTER();
            const uint64_t vd = MK_DESC(sb + SM_V);
            const uint32_t id2 = IDESC_F16_N(64);
            if (elect1()) {
                #pragma unroll
                for (int s = 0; s < 16; s++) {
                    uint32_t a_tmem = tmem + (s >> 3) * 128 +
                                      ((s >> 1) & 3) * 16 + (s & 1) * 8;
                    uint64_t bd = vd + (uint64_t)(s >> 2) * 512 + (s & 3) * 2;
                    mma_f16_ts(tmem + 64, a_tmem, bd, id2, s > 0);
                }
                tc_commit(mbar2);
            }
        }
        mbar_wait(mbar2, hh);
        TC_FENCE_AFTER();

        // ---- drain D to registers (gh0: d 0-31 at col 64; gh1: d 32-63) ----
        {
            uint32_t r[32];
            TC_LD_X32(r, tmem + 64 + gh * 32);
            TC_WAIT_LD();
            #pragma unroll
            for (int t = 0; t < 32; t++)
                acc[t] += __uint_as_float(r[t]);
        }

        // ---- prefetch V half1 (V half0 consumed by MMA2) ----
        if (hh == 0) {
            for (int g = tid; g < 2048; g += 256) {
                const int d = g >> 5, j8 = (g & 31) * 8;
                const float* vs = vbase + (size_t)d * NK + 256 + j8;
                float4 v0 = *(const float4*)(vs);
                float4 v1 = *(const float4*)(vs + 4);
                uint4 pk;
                ((__half2*)&pk)[0] = __floats2half2_rn(v0.x, v0.y);
                ((__half2*)&pk)[1] = __floats2half2_rn(v0.z, v0.w);
                ((__half2*)&pk)[2] = __floats2half2_rn(v1.x, v1.y);
                ((__half2*)&pk)[3] = __floats2half2_rn(v1.z, v1.w);
                *(uint4*)(base + SM_V + v_off(d, j8)) = pk;
            }
            FENCE_ASYNC();
        }
        TC_FENCE_BEFORE();
        __syncthreads();
    }

    // ---- softmax normalization + epilogue ----
    sRow[gh * 128 + row] = rsum;
    __syncthreads();
    if (tid < 128) linv[tid] = 1.f / (sRow[tid] + sRow[128 + tid]);
    __syncthreads();

    float* sO = (float*)(base + SM_K);       // [64][132] floats (K/V dead)
    {
        const float li = linv[row];
        #pragma unroll
        for (int t = 0; t < 32; t++)
            sO[(gh * 32 + t) * 132 + row] = acc[t] * li;
    }
    __syncthreads();
    for (int e = tid; e < 2048; e += 256) {
        const int d = e >> 5, i4 = (e & 31) * 4;
        float4 v = *(const float4*)(sO + d * 132 + i4);
        *(float4*)(gout + ((size_t)b * INNER + h * DHEAD + d) * NQ + i0 + i4) = v;
    }

    __syncthreads();
    if (tid == 0) { mbar_inval(mbar0); mbar_inval(mbar2); }
    __syncthreads();
    if (w == 0) tmem_dealloc(tmem, 256);
#endif  // __CUDA_ARCH_FEAT_SM103_ALL
}

// ---------------------------------------------------------------------------
extern "C" void kernel_launch(void* const* d_in, const int* in_sizes, int n_in,
                              void* d_out, int out_size)
{
    const float* x      = (const float*)d_in[0];
    const float* wq_dw  = (const float*)d_in[1];
    const float* bn_q_g = (const float*)d_in[2];
    const float* bn_q_b = (const float*)d_in[3];
    const float* bn_q_m = (const float*)d_in[4];
    const float* bn_q_v = (const float*)d_in[5];
    const float* wq_pw  = (const float*)d_in[6];
    const float* wkv_dw = (const float*)d_in[7];
    const float* bn_k_g = (const float*)d_in[8];
    const float* bn_k_b = (const float*)d_in[9];
    const float* bn_k_m = (const float*)d_in[10];
    const float* bn_k_v = (const float*)d_in[11];
    const float* wkv_pw = (const float*)d_in[12];
    const float* w_out  = (const float*)d_in[13];
    const float* b_out  = (const float*)d_in[14];
    float* out = (float*)d_out;

    float *p_qdw, *p_kvdw, *p_q, *p_kv, *p_att;
    cudaGetSymbolAddress((void**)&p_qdw,  g_qdw);
    cudaGetSymbolAddress((void**)&p_kvdw, g_kvdw);
    cudaGetSymbolAddress((void**)&p_q,    g_q);
    cudaGetSymbolAddress((void**)&p_kv,   g_kv);
    cudaGetSymbolAddress((void**)&p_att,  g_att);

    cudaFuncSetAttribute(attn_tc_kernel,
                         cudaFuncAttributeMaxDynamicSharedMemorySize, SM_REQ);
    cudaFuncSetAttribute(gemm_tc_kernel,
                         cudaFuncAttributeMaxDynamicSharedMemorySize, GM_REQ);

    // 1. depthwise convs + BN (fused)
    dw_bn_kernel<<<dim3(CDIM, BATCH), 256>>>(
        x, wq_dw, bn_q_g, bn_q_b, bn_q_m, bn_q_v,
        wkv_dw, bn_k_g, bn_k_b, bn_k_m, bn_k_v);

    // 2. pointwise q: (512 x 128) @ (128 x 4096) per batch  [tcgen05 fp16]
    gemm_tc_kernel<<<dim3(NQ / 128, INNER / 128, BATCH), 512, GM_REQ>>>(
        wq_pw, p_qdw, p_q, INNER, NQ, CDIM, nullptr);

    // 3. pointwise kv: (1024 x 128) @ (128 x 512) per batch  [tcgen05 fp16]
    gemm_tc_kernel<<<dim3(NK / 128, (2 * INNER) / 128, BATCH), 512, GM_REQ>>>(
        wkv_pw, p_kvdw, p_kv, 2 * INNER, NK, CDIM, nullptr);

    // 4. fused attention (tcgen05, 2 CTAs/SM, j-halved, D reg-accumulated)
    attn_tc_kernel<<<dim3(NQ / 128, NHEADS, BATCH), 256, SM_REQ>>>(
        p_q, p_kv, p_att);

    // 5. out projection + bias: (128 x 512) @ (512 x 4096) per batch  [tcgen05 fp16]
    gemm_tc_kernel<<<dim3(NQ / 128, CDIM / 128, BATCH), 512, GM_REQ>>>(
        w_out, p_att, out, CDIM, NQ, INNER, b_out);
}

// round 17
// speedup vs baseline: 1.3956x; 1.3956x over previous
#include <cuda_runtime.h>
#include <cuda_bf16.h>
#include <cuda_fp16.h>
#include <math.h>
#include <stdint.h>

#define BATCH 4
#define CDIM 128
#define INNER 512
#define NQ 4096
#define NK 512
#define NHEADS 8
#define DHEAD 64

// ---------------- scratch (static device globals; allocation-free) ----------
// All intermediates are fp16: rounding happens at producer instead of
// consumer (bit-identical to R15 numerics), halving intermediate traffic.
__device__ __half g_qdw[BATCH * CDIM * NQ];     // 4 MB   depthwise-q + BN
__device__ __half g_kvdw[BATCH * CDIM * NK];    // 0.5 MB depthwise-kv + BN
__device__ __half g_q[BATCH * INNER * NQ];      // 16 MB  q (pre-scaled by QSCALE)
__device__ __half g_kv[BATCH * 2 * INNER * NK]; // 4 MB   kv after pointwise
__device__ __half g_att[BATCH * INNER * NQ];    // 16 MB  attention output

#define QSCALE_H (0.125f * 1.44269504088896341f)

// ---------------------------------------------------------------------------
// Kernel 1: both depthwise 3x3x3 convs (stride1 and stride2) + batchnorm.
// Outputs fp16.
// ---------------------------------------------------------------------------
__global__ __launch_bounds__(256) void dw_bn_kernel(
    const float* __restrict__ x,
    const float* __restrict__ wq,
    const float* __restrict__ qg, const float* __restrict__ qb,
    const float* __restrict__ qm, const float* __restrict__ qv,
    const float* __restrict__ wkv,
    const float* __restrict__ kg, const float* __restrict__ kb,
    const float* __restrict__ km, const float* __restrict__ kvvar)
{
    __shared__ float s[18 * 18 * 18];
    __shared__ float swq[27], swkv[27];
    const int c = blockIdx.x, b = blockIdx.y;
    const int tid = threadIdx.x;

    const float* xp = x + ((size_t)(b * CDIM + c)) * NQ;
    for (int idx = tid; idx < 5832; idx += 256) {
        int z = idx / 324; int r = idx - z * 324;
        int y = r / 18;    int xx = r - y * 18;
        z -= 1; y -= 1; xx -= 1;
        float v = 0.f;
        if ((unsigned)z < 16u && (unsigned)y < 16u && (unsigned)xx < 16u)
            v = xp[(z * 16 + y) * 16 + xx];
        s[idx] = v;
    }
    if (tid < 27) { swq[tid] = wq[c * 27 + tid]; swkv[tid] = wkv[c * 27 + tid]; }

    const float qscale = qg[c] * rsqrtf(qv[c] + 1e-5f);
    const float qshift = qb[c] - qm[c] * qscale;
    const float kscale = kg[c] * rsqrtf(kvvar[c] + 1e-5f);
    const float kshift = kb[c] - km[c] * kscale;
    __syncthreads();

    __half* qo = g_qdw + ((size_t)(b * CDIM + c)) * NQ;
    for (int o = tid; o < 4096; o += 256) {
        const int z = o >> 8, y = (o >> 4) & 15, xx = o & 15;
        float sum = 0.f;
        #pragma unroll
        for (int dz = 0; dz < 3; dz++)
            #pragma unroll
            for (int dy = 0; dy < 3; dy++)
                #pragma unroll
                for (int dx = 0; dx < 3; dx++)
                    sum += swq[dz * 9 + dy * 3 + dx] *
                           s[(z + dz) * 324 + (y + dy) * 18 + (xx + dx)];
        qo[o] = __float2half_rn(sum * qscale + qshift);
    }

    __half* ko = g_kvdw + ((size_t)(b * CDIM + c)) * NK;
    for (int o = tid; o < 512; o += 256) {
        const int z = o >> 6, y = (o >> 3) & 7, xx = o & 7;
        float sum = 0.f;
        #pragma unroll
        for (int dz = 0; dz < 3; dz++)
            #pragma unroll
            for (int dy = 0; dy < 3; dy++)
                #pragma unroll
                for (int dx = 0; dx < 3; dx++)
                    sum += swkv[dz * 9 + dy * 3 + dx] *
                           s[(2 * z + dz) * 324 + (2 * y + dy) * 18 + (2 * xx + dx)];
        ko[o] = __float2half_rn(sum * kscale + kshift);
    }
}

// ===========================================================================
// tcgen05 helpers
// ===========================================================================
__device__ __forceinline__ uint32_t s2u(const void* p) {
    uint32_t a;
    asm("{ .reg .u64 t; cvta.to.shared.u64 t, %1; cvt.u32.u64 %0, t; }"
        : "=r"(a) : "l"(p));
    return a;
}
__device__ __forceinline__ uint32_t elect1() {
    uint32_t pred;
    asm volatile("{\n\t.reg .pred p;\n\telect.sync _|p, 0xFFFFFFFF;\n\t"
                 "selp.b32 %0, 1, 0, p;\n\t}" : "=r"(pred));
    return pred;
}
__device__ __forceinline__ void mbar_init(uint32_t mbar, uint32_t cnt) {
    asm volatile("mbarrier.init.shared.b64 [%0], %1;" :: "r"(mbar), "r"(cnt) : "memory");
}
__device__ __forceinline__ void mbar_inval(uint32_t mbar) {
    asm volatile("mbarrier.inval.shared.b64 [%0];" :: "r"(mbar) : "memory");
}
__device__ __forceinline__ void mbar_wait(uint32_t mbar, uint32_t parity) {
    asm volatile(
        "{\n\t.reg .pred P1;\n\t"
        "WL%=:\n\t"
        "mbarrier.try_wait.parity.acquire.cta.shared::cta.b64 P1, [%0], %1, 0x989680;\n\t"
        "@P1 bra.uni WD%=;\n\t"
        "bra.uni WL%=;\n\t"
        "WD%=:\n\t}"
        :: "r"(mbar), "r"(parity) : "memory");
}
__device__ __forceinline__ void tmem_alloc(uint32_t smem_dst, uint32_t ncols) {
    asm volatile("tcgen05.alloc.cta_group::1.sync.aligned.shared::cta.b32 [%0], %1;"
                 :: "r"(smem_dst), "r"(ncols) : "memory");
}
__device__ __forceinline__ void tmem_dealloc(uint32_t tmem, uint32_t ncols) {
    asm volatile("tcgen05.relinquish_alloc_permit.cta_group::1.sync.aligned;");
    asm volatile("tcgen05.dealloc.cta_group::1.sync.aligned.b32 %0, %1;"
                 :: "r"(tmem), "r"(ncols));
}
__device__ __forceinline__ void mma_f16_ss(uint32_t d, uint64_t a, uint64_t b,
                                           uint32_t idesc, uint32_t en) {
    asm volatile(
        "{\n\t.reg .pred p;\n\tsetp.ne.u32 p, %5, 0;\n\t"
        "tcgen05.mma.cta_group::1.kind::f16 [%0], %1, %2, %3, {%4, %4, %4, %4}, p;\n\t}"
        :: "r"(d), "l"(a), "l"(b), "r"(idesc), "r"(0u), "r"(en) : "memory");
}
__device__ __forceinline__ void mma_f16_ts(uint32_t d, uint32_t a_tmem, uint64_t b,
                                           uint32_t idesc, uint32_t en) {
    asm volatile(
        "{\n\t.reg .pred p;\n\tsetp.ne.u32 p, %5, 0;\n\t"
        "tcgen05.mma.cta_group::1.kind::f16 [%0], [%1], %2, %3, {%4, %4, %4, %4}, p;\n\t}"
        :: "r"(d), "r"(a_tmem), "l"(b), "r"(idesc), "r"(0u), "r"(en) : "memory");
}
__device__ __forceinline__ void tc_commit(uint32_t mbar) {
    asm volatile(
        "tcgen05.commit.cta_group::1.mbarrier::arrive::one.shared::cluster.b64 [%0];"
        :: "r"(mbar) : "memory");
}
__device__ __forceinline__ float ex2f(float x) {
    float r;
    asm("ex2.approx.f32 %0, %1;" : "=f"(r) : "f"(x));
    return r;
}
#define TC_FENCE_AFTER()  asm volatile("tcgen05.fence::after_thread_sync;" ::: "memory")
#define TC_FENCE_BEFORE() asm volatile("tcgen05.fence::before_thread_sync;" ::: "memory")
#define TC_WAIT_LD()      asm volatile("tcgen05.wait::ld.sync.aligned;" ::: "memory")
#define TC_WAIT_ST()      asm volatile("tcgen05.wait::st.sync.aligned;" ::: "memory")
#define FENCE_ASYNC()     asm volatile("fence.proxy.async.shared::cta;" ::: "memory")

#define TC_LD_X32(r, addr) \
    asm volatile( \
        "tcgen05.ld.sync.aligned.32x32b.x32.b32 " \
        "{%0, %1, %2, %3, %4, %5, %6, %7, " \
        " %8, %9, %10, %11, %12, %13, %14, %15, " \
        " %16, %17, %18, %19, %20, %21, %22, %23, " \
        " %24, %25, %26, %27, %28, %29, %30, %31}, [%32];" \
        : "=r"((r)[0]),  "=r"((r)[1]),  "=r"((r)[2]),  "=r"((r)[3]), \
          "=r"((r)[4]),  "=r"((r)[5]),  "=r"((r)[6]),  "=r"((r)[7]), \
          "=r"((r)[8]),  "=r"((r)[9]),  "=r"((r)[10]), "=r"((r)[11]), \
          "=r"((r)[12]), "=r"((r)[13]), "=r"((r)[14]), "=r"((r)[15]), \
          "=r"((r)[16]), "=r"((r)[17]), "=r"((r)[18]), "=r"((r)[19]), \
          "=r"((r)[20]), "=r"((r)[21]), "=r"((r)[22]), "=r"((r)[23]), \
          "=r"((r)[24]), "=r"((r)[25]), "=r"((r)[26]), "=r"((r)[27]), \
          "=r"((r)[28]), "=r"((r)[29]), "=r"((r)[30]), "=r"((r)[31]) \
        : "r"(addr))

#define TC_ST_X16(addr, r) \
    asm volatile( \
        "tcgen05.st.sync.aligned.32x32b.x16.b32 [%0], " \
        "{%1, %2, %3, %4, %5, %6, %7, %8, " \
        " %9, %10, %11, %12, %13, %14, %15, %16};" \
        :: "r"(addr), \
           "r"((r)[0]),  "r"((r)[1]),  "r"((r)[2]),  "r"((r)[3]), \
           "r"((r)[4]),  "r"((r)[5]),  "r"((r)[6]),  "r"((r)[7]), \
           "r"((r)[8]),  "r"((r)[9]),  "r"((r)[10]), "r"((r)[11]), \
           "r"((r)[12]), "r"((r)[13]), "r"((r)[14]), "r"((r)[15]) \
        : "memory")

// SW128 smem descriptor base (layout=2, version=1, SBO=64, LBO=1)
#define DESC_BASE ((2ULL << 61) | (1ULL << 46) | (64ULL << 32) | (1ULL << 16))
#define MK_DESC(a) (DESC_BASE | ((uint64_t)((a) >> 4) & 0x3FFFULL))

__device__ __forceinline__ uint32_t sw128(uint32_t o) { return o ^ ((o >> 3) & 0x70); }
// rows x 64 elems (128B rows), SW128
__device__ __forceinline__ uint32_t qk_off(int r, int c) {
    return sw128((uint32_t)r * 128u + (uint32_t)c * 2u);
}
// 128 x (64*ac) 2B elems, blocked-atom, 16 atom-rows per atom-col
__device__ __forceinline__ uint32_t p_off(int i, int j) {
    uint32_t o = ((uint32_t)(i >> 3) + (uint32_t)(j >> 6) * 16u) * 1024u +
                 (uint32_t)(i & 7) * 128u + (uint32_t)(j & 63) * 2u;
    return sw128(o);
}
// 64 x 512 fp16 blocked-atom (8 atom-rows per atom-col)
__device__ __forceinline__ uint32_t v_off(int d, int j) {
    uint32_t o = ((uint32_t)(d >> 3) + (uint32_t)(j >> 6) * 8u) * 1024u +
                 (uint32_t)(d & 7) * 128u + (uint32_t)(j & 63) * 2u;
    return sw128(o);
}

// idesc: dtype F32 (1<<4); atype/btype F16=0; M=128 (8<<24); N bits 17..22
#define IDESC_F16_N(n)  ((1u << 4) | (((n) / 8) << 17) | (8u << 24))

__device__ __forceinline__ __half toh(float v)  { return __float2half_rn(v); }
__device__ __forceinline__ __half toh(__half v) { return v; }

// ===========================================================================
// Kernel 2: tcgen05 GEMM, fp16 operands. A fp32 (weights), B fp32 or fp16,
// C fp32 or fp16 (optional output scale; bias only on fp32 path).
// 66 KB smem -> 3 CTAs/SM. grid (N/128, M/128, BATCH), 512 threads.
// ===========================================================================
#define GM_MISC 0
#define GM_A    1024
#define GM_B    (GM_A + 32768)
#define GM_REQ  (GM_B + 32768 + 1024)

template <typename TB, typename TC>
__global__ __launch_bounds__(512, 1)
void gemm_tc_kernel(const float* __restrict__ A, const TB* __restrict__ Bm,
                    TC* __restrict__ Cm, int M, int N, int K,
                    const float* __restrict__ bias, float oscale)
{
#if defined(__CUDA_ARCH_FEAT_SM103_ALL)
    extern __shared__ char sm_raw[];
    char* base = (char*)(((uintptr_t)sm_raw + 1023) & ~(uintptr_t)1023);
    const uint32_t sb = s2u(base);

    const int tid = threadIdx.x, w = tid >> 5, lane = tid & 31;
    const int sub = w & 3, grp = w >> 2;
    const int row = sub * 32 + lane;
    const int n0 = blockIdx.x * 128, m0 = blockIdx.y * 128, bz = blockIdx.z;

    const uint32_t misc = sb + GM_MISC;
    const uint32_t mbar = misc + 8;
    if (w == 0) tmem_alloc(misc, 128);
    if (tid == 0) mbar_init(mbar, 1);
    __syncthreads();
    uint32_t tmem;
    asm volatile("ld.shared.b32 %0, [%1];" : "=r"(tmem) : "r"(misc));

    const TB* Bp = Bm + (size_t)bz * K * N;
    TC* Cp = Cm + (size_t)bz * M * N;
    const int nchunks = K >> 7;

    for (int kc = 0; kc < nchunks; kc++) {
        const int k0 = kc << 7;
        // ---- load A tile [128 m][128 k] fp32 -> fp16, blocked-atom ----
        for (int g = tid; g < 2048; g += 512) {
            const int m = g >> 4, kg = (g & 15) * 8;
            const float* as = A + (size_t)(m0 + m) * K + k0 + kg;
            float4 a0 = *(const float4*)(as);
            float4 a1 = *(const float4*)(as + 4);
            uint4 pk;
            ((__half2*)&pk)[0] = __floats2half2_rn(a0.x, a0.y);
            ((__half2*)&pk)[1] = __floats2half2_rn(a0.z, a0.w);
            ((__half2*)&pk)[2] = __floats2half2_rn(a1.x, a1.y);
            ((__half2*)&pk)[3] = __floats2half2_rn(a1.z, a1.w);
            *(uint4*)(base + GM_A + p_off(m, kg)) = pk;
        }
        // ---- load B tile transposed: Bs[n][k] = B[k0+k][n0+n] ----
        for (int g = tid; g < 2048; g += 512) {
            const int n = g & 127, kg = (g >> 7) * 8;
            const TB* bs = Bp + (size_t)(k0 + kg) * N + n0 + n;
            uint4 pk;
            #pragma unroll
            for (int t = 0; t < 4; t++) {
                __half lo = toh(bs[(size_t)(2 * t) * N]);
                __half hi = toh(bs[(size_t)(2 * t + 1) * N]);
                ((__half2*)&pk)[t] = __halves2half2(lo, hi);
            }
            *(uint4*)(base + GM_B + p_off(n, kg)) = pk;
        }
        FENCE_ASYNC();
        __syncthreads();

        // ---- single-term fp16 MMA over this K-chunk (8 k-steps) ----
        if (w == 0) {
            TC_FENCE_AFTER();
            const uint64_t ad = MK_DESC(sb + GM_A);
            const uint64_t bd = MK_DESC(sb + GM_B);
            const uint32_t id = IDESC_F16_N(128);
            if (elect1()) {
                #pragma unroll
                for (int s = 0; s < 8; s++) {
                    uint64_t doff = (uint64_t)(s >> 2) * 1024 + (s & 3) * 2;
                    mma_f16_ss(tmem, ad + doff, bd + doff, id, !(kc == 0 && s == 0));
                }
                tc_commit(mbar);
            }
        }
        mbar_wait(mbar, kc & 1);
    }
    TC_FENCE_AFTER();

    // ---- epilogue: LDTM 32 cols per warp-group, scale (+bias), store ----
    {
        uint32_t r[32];
        TC_LD_X32(r, tmem + grp * 32);
        TC_WAIT_LD();
        TC_FENCE_BEFORE();
        if constexpr (sizeof(TC) == 2) {
            __half* cp = (__half*)(Cp + (size_t)(m0 + row) * N + n0 + grp * 32);
            #pragma unroll
            for (int t8 = 0; t8 < 32; t8 += 8) {
                uint4 st;
                #pragma unroll
                for (int t = 0; t < 4; t++) {
                    float v0 = __uint_as_float(r[t8 + 2 * t]) * oscale;
                    float v1 = __uint_as_float(r[t8 + 2 * t + 1]) * oscale;
                    ((__half2*)&st)[t] = __floats2half2_rn(v0, v1);
                }
                *(uint4*)(cp + t8) = st;
            }
        } else {
            const float bb = bias ? bias[m0 + row] : 0.f;
            float* cp = (float*)(Cp + (size_t)(m0 + row) * N + n0 + grp * 32);
            #pragma unroll
            for (int t = 0; t < 32; t += 4) {
                float4 v = make_float4(__uint_as_float(r[t]) + bb,
                                       __uint_as_float(r[t + 1]) + bb,
                                       __uint_as_float(r[t + 2]) + bb,
                                       __uint_as_float(r[t + 3]) + bb);
                *(float4*)(cp + t) = v;
            }
        }
    }

    __syncthreads();
    if (tid == 0) mbar_inval(mbar);
    __syncthreads();
    if (w == 0) tmem_dealloc(tmem, 128);
#endif
}

// smem regions for attention (relative to 1024-aligned base)
#define SM_MISC 0
#define SM_Q    4096                 // 16 KB: Q fp16 [128 i][64 d]
#define SM_K    (SM_Q + 16384)       // 64 KB: K fp16 [512 j][64 d]   -> sO stage
#define SM_V    (SM_K + 65536)       // 64 KB: V fp16 [64 d][512 j] blocked-atom
#define SM_REQ  (SM_V + 65536 + 1024)

// ===========================================================================
// Kernel 3: tcgen05 fused attention (R15 structure), fp16 in/out tensors.
// g_q is pre-scaled by QSCALE (folded into q-GEMM). fp32 dots in TMEM;
// P fp16x2 in place per warp-quarter; D (fp32) at word-cols 448-511.
// One CTA = (b, h, 128 q rows). grid (32, 8, 4), 512 threads.
// ===========================================================================
__global__ __launch_bounds__(512, 1)
void attn_tc_kernel(const __half* __restrict__ gq,
                    const __half* __restrict__ gkv,
                    __half* __restrict__ gout)
{
#if defined(__CUDA_ARCH_FEAT_SM103_ALL)
    extern __shared__ char sm_raw[];
    char* base = (char*)(((uintptr_t)sm_raw + 1023) & ~(uintptr_t)1023);
    const uint32_t sb = s2u(base);

    const int tid = threadIdx.x, w = tid >> 5, lane = tid & 31;
    const int sub = w & 3, grp = w >> 2;     // subpartition / 128-j quarter
    const int row = sub * 32 + lane;         // q row owned in TMEM
    const int i0 = blockIdx.x * 128;
    const int h  = blockIdx.y;
    const int b  = blockIdx.z;

    const uint32_t misc  = sb + SM_MISC;
    const uint32_t mbar0 = misc + 8;
    const uint32_t mbar1 = misc + 16;
    const uint32_t mbar2 = misc + 24;
    float* sRow = (float*)(base + SM_MISC + 1024);   // [4][128]
    float* linv = (float*)(base + SM_MISC + 3072);   // [128]

    if (w == 0) tmem_alloc(misc, 512);
    if (tid == 0) { mbar_init(mbar0, 1); mbar_init(mbar1, 1); mbar_init(mbar2, 1); }
    __syncthreads();
    uint32_t tmem;
    asm volatile("ld.shared.b32 %0, [%1];" : "=r"(tmem) : "r"(misc));

    const __half* qbase = gq  + ((size_t)b * INNER + h * DHEAD) * NQ + i0;
    const __half* kbase = gkv + ((size_t)b * 2 * INNER + h * DHEAD) * NK;
    const __half* vbase = kbase + (size_t)INNER * NK;

    // ---- load Q fp16 (transpose [d][i]->[i][d]; already QSCALE-scaled) ----
    for (int g = tid; g < 1024; g += 512) {
        const int i = g & 127, d0 = (g >> 7) * 8;
        uint4 pk;
        #pragma unroll
        for (int t = 0; t < 4; t++) {
            __half lo = qbase[(size_t)(d0 + 2 * t) * NQ + i];
            __half hi = qbase[(size_t)(d0 + 2 * t + 1) * NQ + i];
            ((__half2*)&pk)[t] = __halves2half2(lo, hi);
        }
        *(uint4*)(base + SM_Q + qk_off(i, d0)) = pk;
    }
    // ---- load K fp16 (transpose [d][j]->[j][d]) ----
    for (int g = tid; g < 4096; g += 512) {
        const int j = g & 511, d0 = (g >> 9) * 8;
        uint4 pk;
        #pragma unroll
        for (int t = 0; t < 4; t++) {
            __half lo = kbase[(size_t)(d0 + 2 * t) * NK + j];
            __half hi = kbase[(size_t)(d0 + 2 * t + 1) * NK + j];
            ((__half2*)&pk)[t] = __halves2half2(lo, hi);
        }
        *(uint4*)(base + SM_K + qk_off(j, d0)) = pk;
    }
    FENCE_ASYNC();
    __syncthreads();

    // ---- MMA1: dots = Q K^T, fp32 accum, two N=256 chunks (4 K-steps) ----
    if (w == 0) {
        const uint64_t qd = MK_DESC(sb + SM_Q);
        const uint32_t id1 = IDESC_F16_N(256);
        if (elect1()) {
            #pragma unroll
            for (int c = 0; c < 2; c++) {
                const uint32_t dst = tmem + c * 256;
                const uint64_t kd = MK_DESC(sb + SM_K + c * 32768);
                #pragma unroll
                for (int s = 0; s < 4; s++)
                    mma_f16_ss(dst, qd + s * 2, kd + s * 2, id1, s > 0);
                tc_commit(c ? mbar1 : mbar0);
            }
        }
    }

    // ---- load V fp16 [d][j] blocked-atom: straight uint4 copy ----
    for (int g = tid; g < 4096; g += 512) {
        const int d = g >> 6, j8 = (g & 63) * 8;
        uint4 pk = *(const uint4*)(vbase + (size_t)d * NK + j8);
        *(uint4*)(base + SM_V + v_off(d, j8)) = pk;
    }
    FENCE_ASYNC();

    // ---- per-chunk: LDTM 32 fp32 dots + exp + row-sum + STTM 16 P words.
    //      P chunk c8 -> word-cols [128*grp + 16*c8): inside own read region.
    mbar_wait(grp < 2 ? mbar0 : mbar1, 0);
    TC_FENCE_AFTER();
    {
        float rsum = 0.f;
        for (int c8 = 0; c8 < 4; c8++) {
            uint32_t r[32], pk[16];
            TC_LD_X32(r, tmem + grp * 128 + c8 * 32);
            TC_WAIT_LD();
            #pragma unroll
            for (int t = 0; t < 16; t++) {
                float e0 = ex2f(__uint_as_float(r[2 * t]));
                float e1 = ex2f(__uint_as_float(r[2 * t + 1]));
                rsum += e0 + e1;
                __half2 h2 = __floats2half2_rn(e0, e1);
                pk[t] = *(uint32_t*)&h2;
            }
            TC_ST_X16(tmem + grp * 128 + c8 * 16, pk);
            TC_WAIT_ST();
        }
        sRow[grp * 128 + row] = rsum;
        TC_FENCE_BEFORE();
    }
    __syncthreads();
    if (tid < 128)
        linv[tid] = 1.f / (sRow[tid] + sRow[128 + tid] +
                           sRow[256 + tid] + sRow[384 + tid]);
    __syncthreads();

    // ---- MMA2 (TS): D = P(tmem) @ V^T, K=512 (32 steps), D at cols 448 ----
    if (w == 0) {
        TC_FENCE_AFTER();
        const uint64_t vd = MK_DESC(sb + SM_V);
        const uint32_t id2 = IDESC_F16_N(64);
        if (elect1()) {
            #pragma unroll
            for (int s = 0; s < 32; s++) {
                uint32_t a_tmem = tmem + (s >> 3) * 128 + (s & 7) * 8;
                uint64_t bd = vd + (uint64_t)(s >> 2) * 512 + (s & 3) * 2;
                mma_f16_ts(tmem + 448, a_tmem, bd, id2, s > 0);
            }
            tc_commit(mbar2);
        }
    }
    mbar_wait(mbar2, 0);
    TC_FENCE_AFTER();

    // ---- epilogue: scale by 1/l, stage sO[d][i] in SM_K, fp16 store ----
    float* sO = (float*)(base + SM_K);       // [64][132] floats
    if (grp < 2) {
        const int colb = grp * 32;
        uint32_t r[32];
        TC_LD_X32(r, tmem + 448 + colb);
        TC_WAIT_LD();
        TC_FENCE_BEFORE();
        const float li = linv[row];
        #pragma unroll
        for (int t = 0; t < 32; t++)
            sO[(colb + t) * 132 + row] = __uint_as_float(r[t]) * li;
    }
    __syncthreads();
    for (int e = tid; e < 2048; e += 512) {
        const int d = e >> 5, i4 = (e & 31) * 4;
        float4 v = *(const float4*)(sO + d * 132 + i4);
        uint2 st;
        ((__half2*)&st)[0] = __floats2half2_rn(v.x, v.y);
        ((__half2*)&st)[1] = __floats2half2_rn(v.z, v.w);
        *(uint2*)(gout + ((size_t)b * INNER + h * DHEAD + d) * NQ + i0 + i4) = st;
    }

    __syncthreads();
    if (tid == 0) { mbar_inval(mbar0); mbar_inval(mbar1); mbar_inval(mbar2); }
    __syncthreads();
    if (w == 0) tmem_dealloc(tmem, 512);
#endif  // __CUDA_ARCH_FEAT_SM103_ALL
}

// ---------------------------------------------------------------------------
extern "C" void kernel_launch(void* const* d_in, const int* in_sizes, int n_in,
                              void* d_out, int out_size)
{
    const float* x      = (const float*)d_in[0];
    const float* wq_dw  = (const float*)d_in[1];
    const float* bn_q_g = (const float*)d_in[2];
    const float* bn_q_b = (const float*)d_in[3];
    const float* bn_q_m = (const float*)d_in[4];
    const float* bn_q_v = (const float*)d_in[5];
    const float* wq_pw  = (const float*)d_in[6];
    const float* wkv_dw = (const float*)d_in[7];
    const float* bn_k_g = (const float*)d_in[8];
    const float* bn_k_b = (const float*)d_in[9];
    const float* bn_k_m = (const float*)d_in[10];
    const float* bn_k_v = (const float*)d_in[11];
    const float* wkv_pw = (const float*)d_in[12];
    const float* w_out  = (const float*)d_in[13];
    const float* b_out  = (const float*)d_in[14];
    float* out = (float*)d_out;

    __half *p_qdw, *p_kvdw, *p_q, *p_kv, *p_att;
    cudaGetSymbolAddress((void**)&p_qdw,  g_qdw);
    cudaGetSymbolAddress((void**)&p_kvdw, g_kvdw);
    cudaGetSymbolAddress((void**)&p_q,    g_q);
    cudaGetSymbolAddress((void**)&p_kv,   g_kv);
    cudaGetSymbolAddress((void**)&p_att,  g_att);

    cudaFuncSetAttribute(attn_tc_kernel,
                         cudaFuncAttributeMaxDynamicSharedMemorySize, SM_REQ);
    cudaFuncSetAttribute(gemm_tc_kernel<__half, __half>,
                         cudaFuncAttributeMaxDynamicSharedMemorySize, GM_REQ);
    cudaFuncSetAttribute(gemm_tc_kernel<__half, float>,
                         cudaFuncAttributeMaxDynamicSharedMemorySize, GM_REQ);

    // 1. depthwise convs + BN (fused), fp16 outputs
    dw_bn_kernel<<<dim3(CDIM, BATCH), 256>>>(
        x, wq_dw, bn_q_g, bn_q_b, bn_q_m, bn_q_v,
        wkv_dw, bn_k_g, bn_k_b, bn_k_m, bn_k_v);

    // 2. pointwise q (QSCALE folded): (512x128) @ (128x4096) per batch
    gemm_tc_kernel<__half, __half>
        <<<dim3(NQ / 128, INNER / 128, BATCH), 512, GM_REQ>>>(
        wq_pw, p_qdw, p_q, INNER, NQ, CDIM, nullptr, QSCALE_H);

    // 3. pointwise kv: (1024x128) @ (128x512) per batch
    gemm_tc_kernel<__half, __half>
        <<<dim3(NK / 128, (2 * INNER) / 128, BATCH), 512, GM_REQ>>>(
        wkv_pw, p_kvdw, p_kv, 2 * INNER, NK, CDIM, nullptr, 1.0f);

    // 4. fused attention (tcgen05, fp16 tensors, fp32 dots, D at 448)
    attn_tc_kernel<<<dim3(NQ / 128, NHEADS, BATCH), 512, SM_REQ>>>(
        p_q, p_kv, p_att);

    // 5. out projection + bias: (128x512) @ (512x4096) per batch, fp32 out
    gemm_tc_kernel<__half, float>
        <<<dim3(NQ / 128, CDIM / 128, BATCH), 512, GM_REQ>>>(
        w_out, p_att, out, CDIM, NQ, INNER, b_out, 1.0f);
}